// round 16
// baseline (speedup 1.0000x reference)
#include <cuda_runtime.h>
#include <cuda_fp16.h>
#include <math.h>
#include <stdint.h>

#define B 64
#define T 128
#define V 10000
#define E 1024
#define H 1024
#define G4 4096
#define L 2
#define KDIM 1024

// ---------------- scratch (device globals) ----------------------------------
__device__ float g_gx[(size_t)B * T * G4];
__device__ int   g_len[B];
__device__ unsigned g_slots[128 * 32];           // per-CTA barrier slots, 128B apart
__device__ __half g_xhi[(size_t)B * T * E];
__device__ __half g_whi[(size_t)V * H];
__device__ __half g_hbf[2][B * H];               // fp16 hidden state (pingpong)
__device__ __half g_wrhi[(size_t)G4 * H];        // gate-interleaved Whh (fp16)

// ---------------- PTX helpers (portable sm_80+ PTX) --------------------------
__device__ __forceinline__ uint32_t smem_u32(const void* p) {
    uint32_t a;
    asm("{ .reg .u64 t; cvta.to.shared.u64 t, %1; cvt.u32.u64 %0, t; }" : "=r"(a) : "l"(p));
    return a;
}
__device__ __forceinline__ void ldmx4(uint32_t r[4], uint32_t addr) {
    asm volatile("ldmatrix.sync.aligned.m8n8.x4.shared.b16 {%0,%1,%2,%3}, [%4];"
                 : "=r"(r[0]), "=r"(r[1]), "=r"(r[2]), "=r"(r[3]) : "r"(addr));
}
__device__ __forceinline__ void mma16816h(float d[4], const uint32_t a[4], const uint32_t b[2]) {
    asm volatile("mma.sync.aligned.m16n8k16.row.col.f32.f16.f16.f32 "
                 "{%0,%1,%2,%3}, {%4,%5,%6,%7}, {%8,%9}, {%0,%1,%2,%3};"
                 : "+f"(d[0]), "+f"(d[1]), "+f"(d[2]), "+f"(d[3])
                 : "r"(a[0]), "r"(a[1]), "r"(a[2]), "r"(a[3]), "r"(b[0]), "r"(b[1]));
}
__device__ __forceinline__ void cp16(uint32_t saddr, const void* gaddr) {
    asm volatile("cp.async.cg.shared.global [%0], [%1], 16;" :: "r"(saddr), "l"(gaddr));
}
__device__ __forceinline__ void cp16z(uint32_t saddr, const void* gaddr, int nbytes) {
    asm volatile("cp.async.cg.shared.global [%0], [%1], 16, %2;"
                 :: "r"(saddr), "l"(gaddr), "r"(nbytes));
}
__device__ __forceinline__ void cp_commit() {
    asm volatile("cp.async.commit_group;" ::: "memory");
}
template <int N>
__device__ __forceinline__ void cp_wait() {
    asm volatile("cp.async.wait_group %0;" :: "n"(N) : "memory");
}

// ---------------- small kernels ----------------------------------------------
__global__ void lengths_kernel(const int* __restrict__ mask) {
    int b = blockIdx.x;
    int v = mask[b * T + threadIdx.x];
#pragma unroll
    for (int o = 16; o > 0; o >>= 1) v += __shfl_down_sync(0xffffffffu, v, o);
    __shared__ int sh[4];
    if ((threadIdx.x & 31) == 0) sh[threadIdx.x >> 5] = v;
    __syncthreads();
    if (threadIdx.x == 0) g_len[b] = sh[0] + sh[1] + sh[2] + sh[3];
}

__global__ void embed_kernel(const int* __restrict__ ids, const float* __restrict__ emb) {
    int r = blockIdx.x;
    int id = __ldg(&ids[r]);
    const float4* s = reinterpret_cast<const float4*>(emb) + (size_t)id * (E / 4);
    float4 v = s[threadIdx.x];
    __half2* hp = reinterpret_cast<__half2*>(g_xhi) + (size_t)r * (E / 2) + 2 * threadIdx.x;
    hp[0] = __half2(__float2half_rn(v.x), __float2half_rn(v.y));
    hp[1] = __half2(__float2half_rn(v.z), __float2half_rn(v.w));
}

__global__ void zero_hb() {
    int i = blockIdx.x * blockDim.x + threadIdx.x;
    if (i < 128 * 32) g_slots[i] = 0u;
    if (i < B * H) {
        __half z = __float2half_rn(0.f);
        g_hbf[0][i] = z; g_hbf[1][i] = z;
    }
}

__global__ void convert_w(const float* __restrict__ wsrc, int n4) {
    int i = blockIdx.x * blockDim.x + threadIdx.x;
    if (i >= n4) return;
    float4 v = reinterpret_cast<const float4*>(wsrc)[i];
    __half2* hp = reinterpret_cast<__half2*>(g_whi) + 2 * i;
    hp[0] = __half2(__float2half_rn(v.x), __float2half_rn(v.y));
    hp[1] = __half2(__float2half_rn(v.z), __float2half_rn(v.w));
}

__global__ void reorder_whh(const float* __restrict__ Whh) {
    int r = blockIdx.x;
    int j = r >> 2, g = r & 3;
    const float4* src = reinterpret_cast<const float4*>(Whh + (size_t)(g * H + j) * H);
    int i = threadIdx.x;
    float4 v = src[i];
    __half2* hp = reinterpret_cast<__half2*>(g_wrhi + (size_t)r * H) + 2 * i;
    hp[0] = __half2(__float2half_rn(v.x), __float2half_rn(v.y));
    hp[1] = __half2(__float2half_rn(v.z), __float2half_rn(v.w));
}

// ---------------- fp16 1-pass GEMM, 3-stage cp.async, 1 sync/chunk, occ=2 ---
#define SSTR 40
#define MAT_BYTES (128 * SSTR * 2)      // 10240 B
#define STG_BYTES (2 * MAT_BYTES)       // A|W = 20480 B per stage
#define NSTAGE 3
#define GEMM_SMEM (NSTAGE * STG_BYTES)  // 61440 B

__global__ void __launch_bounds__(256, 2) mma_gemm(
    float* __restrict__ Cout, const float* __restrict__ b1,
    const float* __restrict__ b2, int Ncols, int ldc, int mode)
{
    extern __shared__ char dsm[];
    float* __restrict__ C = (mode == 0) ? g_gx : Cout;

    const int tid  = threadIdx.x;
    const int wid  = tid >> 5;
    const int lane = tid & 31;
    const int row0 = blockIdx.y * 128;
    const int col0 = blockIdx.x * 128;
    const int wm0  = (wid >> 2) * 64;
    const int wn0  = (wid & 3) * 32;

    const uint32_t smem0 = smem_u32(dsm);

    const int r0t = tid >> 2, r1t = (256 + tid) >> 2;
    const int qt  = tid & 3;

    auto issue = [&](int ch) {
        const uint32_t sb = smem0 + (ch % NSTAGE) * STG_BYTES;
        const int kb = ch * 32;
#pragma unroll
        for (int s = 0; s < 2; s++) {
            int r = (s == 0) ? r0t : r1t;
            uint32_t so = (uint32_t)((r * SSTR + qt * 8) * 2);
            size_t ga = (size_t)(row0 + r) * KDIM + kb + qt * 8;
            cp16(sb + so, g_xhi + ga);
            int n = col0 + r;
            int ok = (n < Ncols) ? 16 : 0;
            size_t gb = (size_t)(ok ? n : 0) * KDIM + kb + qt * 8;
            cp16z(sb + MAT_BYTES + so, g_whi + gb, ok);
        }
        cp_commit();
    };

    float acc[4][4][4];
#pragma unroll
    for (int mi = 0; mi < 4; mi++)
#pragma unroll
        for (int ni = 0; ni < 4; ni++)
#pragma unroll
            for (int q = 0; q < 4; q++) acc[mi][ni][q] = 0.f;

    const int NCH = KDIM / 32;
    issue(0);
    issue(1);

    const int arow = wm0 + (lane & 7) + ((lane >> 3) & 1) * 8;
    const int acol0 = (lane >> 4) * 8;
    const int brow = wn0 + (lane & 7) + ((lane >> 4) & 1) * 8;
    const int bcol0 = ((lane >> 3) & 1) * 8;

    for (int ch = 0; ch < NCH; ch++) {
        cp_wait<1>();
        __syncthreads();

        if (ch + 2 < NCH) issue(ch + 2);

        const uint32_t sb = smem0 + (ch % NSTAGE) * STG_BYTES;

#pragma unroll
        for (int ks = 0; ks < 2; ks++) {
            uint32_t A[4][4], Bq[4], Bh[4][2];
#pragma unroll
            for (int mi = 0; mi < 4; mi++)
                ldmx4(A[mi], sb + (uint32_t)(((arow + mi * 16) * SSTR + ks * 16 + acol0) * 2));
#pragma unroll
            for (int p = 0; p < 2; p++) {
                ldmx4(Bq, sb + MAT_BYTES +
                      (uint32_t)(((brow + p * 16) * SSTR + ks * 16 + bcol0) * 2));
                Bh[2 * p][0] = Bq[0]; Bh[2 * p][1] = Bq[1];
                Bh[2 * p + 1][0] = Bq[2]; Bh[2 * p + 1][1] = Bq[3];
            }
#pragma unroll
            for (int mi = 0; mi < 4; mi++)
#pragma unroll
                for (int ni = 0; ni < 4; ni++)
                    mma16816h(acc[mi][ni], A[mi], Bh[ni]);
        }
    }

#pragma unroll
    for (int ni = 0; ni < 4; ni++) {
        int col = col0 + wn0 + ni * 8 + (lane & 3) * 2;
        if (col >= Ncols) continue;
        float bx = b1[col], by = b1[col + 1];
        if (b2) { bx += b2[col]; by += b2[col + 1]; }
#pragma unroll
        for (int mi = 0; mi < 4; mi++) {
            int row = row0 + wm0 + mi * 16 + (lane >> 2);
            float2 v0 = make_float2(acc[mi][ni][0] + bx, acc[mi][ni][1] + by);
            float2 v1 = make_float2(acc[mi][ni][2] + bx, acc[mi][ni][3] + by);
            *reinterpret_cast<float2*>(&C[(size_t)row * ldc + col])       = v0;
            *reinterpret_cast<float2*>(&C[(size_t)(row + 8) * ldc + col]) = v1;
        }
    }
}

// ---------------- persistent fp16 LSTM recurrence ---------------------------
// Distinct-slot grid barrier (no atomic serialization); staggered h loads.
#define WSTR 1032
#define ASTR 1032
#define OFF_WH 0
#define OFF_AH (32 * WSTR * 2)                    // 66048
#define OFF_SS (OFF_AH + 64 * ASTR * 2)           // 198144
#define OFF_GX (OFF_SS + 64 * 36 * 4)             // 207360
#define OFF_HL (OFF_GX + 64 * 32 * 4)             // 215552
#define OFF_CL (OFF_HL + 512 * 4)                 // 217600
#define SMEM_P (OFF_CL + 512 * 4)                 // 219648

__global__ void __launch_bounds__(256, 1) tc_persist(
    float* __restrict__ hs_out, float* __restrict__ cs_out)
{
    extern __shared__ char dsm[];
    __half* sWh = reinterpret_cast<__half*>(dsm + OFF_WH);
    __half* sAh = reinterpret_cast<__half*>(dsm + OFF_AH);
    float (*Ssm)[36] = reinterpret_cast<float(*)[36]>(dsm + OFF_SS);
    float* gxs  = reinterpret_cast<float*>(dsm + OFF_GX);
    float* hloc = reinterpret_cast<float*>(dsm + OFF_HL);
    float* cloc = reinterpret_cast<float*>(dsm + OFF_CL);

    const int tid  = threadIdx.x;
    const int wid  = tid >> 5;
    const int lane = tid & 31;
    const int jblk = blockIdx.x;

    const uint32_t baseAh = smem_u32(sAh);
    const uint32_t baseWh = smem_u32(sWh);
    const uint32_t baseGx = smem_u32(gxs);

    for (int i = tid; i < 32 * 128; i += 256) {
        int r = i >> 7, q = i & 127;
        size_t gb = (size_t)(jblk * 32 + r) * H + q * 8;
        *reinterpret_cast<uint4*>(sWh + r * WSTR + q * 8) = *reinterpret_cast<const uint4*>(g_wrhi + gb);
    }
    hloc[tid] = 0.f; hloc[tid + 256] = 0.f;
    cloc[tid] = 0.f; cloc[tid + 256] = 0.f;
    __syncthreads();

    const int b0 = tid >> 3, b1 = (tid + 256) >> 3;
    const int jl = tid & 7;
    const int j  = jblk * 8 + jl;
    const int len0 = g_len[b0], len1 = g_len[b1];

    const int arow  = (wid & 3) * 16 + (lane & 7) + ((lane >> 3) & 1) * 8;
    const int acol0 = (lane >> 4) * 8;
    const int brow  = (wid >> 2) * 16 + (lane & 7) + ((lane >> 4) & 1) * 8;
    const int bcol0 = ((lane >> 3) & 1) * 8;

    const int gb0 = tid >> 3,         gg0 = (tid >> 1) & 3,         gh0 = tid & 1;
    const int gb1 = (tid + 256) >> 3, gg1 = ((tid + 256) >> 1) & 3, gh1 = tid & 1;

    unsigned* myslot  = &g_slots[jblk * 32];
    unsigned* pollsl  = &g_slots[(tid & 127) * 32];

    for (int t = 0; t < T; t++) {
        const __half* __restrict__ hbh = g_hbf[t & 1];

        auto issue_h = [&](int g) {
#pragma unroll
            for (int i = 0; i < 8; i++) {
                int idx = i * 256 + tid;
                int r = idx >> 5, q = idx & 31;
                uint32_t so = (uint32_t)((r * ASTR + g * 256 + q * 8) * 2);
                cp16(baseAh + so, hbh + (size_t)r * H + g * 256 + q * 8);
            }
            cp_commit();
        };

        // staggered issue: g0, g1, gx up front; g2/g3 after compute starts
        issue_h(0);
        issue_h(1);
        {
            const float* gsrc = g_gx + (size_t)t * G4;
            cp16(baseGx + (uint32_t)((gb0 * 32 + gg0 * 8 + gh0 * 4) * 4),
                 gsrc + (size_t)gb0 * T * G4 + gg0 * H + jblk * 8 + gh0 * 4);
            cp16(baseGx + (uint32_t)((gb1 * 32 + gg1 * 8 + gh1 * 4) * 4),
                 gsrc + (size_t)gb1 * T * G4 + gg1 * H + jblk * 8 + gh1 * 4);
            cp_commit();
        }

        float acc[2][4];
#pragma unroll
        for (int ni = 0; ni < 2; ni++)
#pragma unroll
            for (int q = 0; q < 4; q++) acc[ni][q] = 0.f;

#pragma unroll
        for (int g = 0; g < 4; g++) {
            // pending before wait: g0:[h0,h1,gx] g1:[h1,gx,h2] g2:[gx,h2,h3] g3:[h3]
            if (g == 0) cp_wait<2>();
            else if (g == 1) cp_wait<2>();
            else if (g == 2) cp_wait<1>();
            else cp_wait<0>();
            __syncthreads();

            if (g < 2) issue_h(g + 2);

#pragma unroll
            for (int ks = 0; ks < 16; ks++) {
                int kc = g * 256 + ks * 16;
                uint32_t Ah[4], Bq[4], Bh[2][2];
                ldmx4(Ah, baseAh + (uint32_t)((arow * ASTR + kc + acol0) * 2));
                ldmx4(Bq, baseWh + (uint32_t)((brow * WSTR + kc + bcol0) * 2));
                Bh[0][0] = Bq[0]; Bh[0][1] = Bq[1];
                Bh[1][0] = Bq[2]; Bh[1][1] = Bq[3];
#pragma unroll
                for (int ni = 0; ni < 2; ni++)
                    mma16816h(acc[ni], Ah, Bh[ni]);
            }
        }

        __syncthreads();
        {
            int row = (wid & 3) * 16 + (lane >> 2);
            int cc  = (wid >> 2) * 16 + (lane & 3) * 2;
#pragma unroll
            for (int ni = 0; ni < 2; ni++) {
                int c = cc + ni * 8;
                Ssm[row][c]         = acc[ni][0];
                Ssm[row][c + 1]     = acc[ni][1];
                Ssm[row + 8][c]     = acc[ni][2];
                Ssm[row + 8][c + 1] = acc[ni][3];
            }
        }
        __syncthreads();

        __half* __restrict__ hbho = g_hbf[(t + 1) & 1];
        float xo[2];

#pragma unroll
        for (int ii = 0; ii < 2; ii++) {
            int b   = ii ? b1 : b0;
            int idx = tid + ii * 256;
            float iv = Ssm[b][4 * jl + 0] + gxs[b * 32 + jl];
            float fv = Ssm[b][4 * jl + 1] + gxs[b * 32 + 8 + jl];
            float gv = Ssm[b][4 * jl + 2] + gxs[b * 32 + 16 + jl];
            float ov = Ssm[b][4 * jl + 3] + gxs[b * 32 + 24 + jl];

            float c_old = cloc[idx];
            float h_old = hloc[idx];

            float si = 1.f / (1.f + expf(-iv));
            float sf = 1.f / (1.f + expf(-fv));
            float so = 1.f / (1.f + expf(-ov));
            float cn = fmaf(sf, c_old, si * tanhf(gv));
            float hn = so * tanhf(cn);

            bool ok = t < (ii ? len1 : len0);
            float cw = ok ? cn : c_old;
            float hw = ok ? hn : h_old;
            cloc[idx] = cw;
            hloc[idx] = hw;
            hbho[b * H + j] = __float2half_rn(hw);
            xo[ii] = ok ? hn : 0.f;
        }

        if (t + 1 < T) {
            __syncthreads();     // all hbf stores issued block-wide
            if (tid == 0) {
                __threadfence();
                asm volatile("st.release.gpu.u32 [%0], %1;"
                             :: "l"(myslot), "r"((unsigned)(t + 1)) : "memory");
            }
            // non-critical store overlapped with the poll
            g_xhi[((size_t)b0 * T + t) * E + j] = __float2half_rn(xo[0]);
            g_xhi[((size_t)b1 * T + t) * E + j] = __float2half_rn(xo[1]);
            if (tid < 128) {
                unsigned v;
                do {
                    asm volatile("ld.acquire.gpu.u32 %0, [%1];" : "=r"(v) : "l"(pollsl));
                    if (v >= (unsigned)(t + 1)) break;
                    __nanosleep(32);
                } while (true);
            }
            __syncthreads();
        } else {
            g_xhi[((size_t)b0 * T + t) * E + j] = __float2half_rn(xo[0]);
            g_xhi[((size_t)b1 * T + t) * E + j] = __float2half_rn(xo[1]);
        }
    }

    hs_out[b0 * H + j] = hloc[tid];
    hs_out[b1 * H + j] = hloc[tid + 256];
    cs_out[b0 * H + j] = cloc[tid];
    cs_out[b1 * H + j] = cloc[tid + 256];
}

// ---------------- launch ------------------------------------------------------
extern "C" void kernel_launch(void* const* d_in, const int* in_sizes, int n_in,
                              void* d_out, int out_size)
{
    const int*   ids  = (const int*)d_in[0];
    const int*   mask = (const int*)d_in[1];
    const float* emb  = (const float*)d_in[2];
    const float* Wih  = (const float*)d_in[3];
    const float* Whh  = (const float*)d_in[4];
    const float* bih  = (const float*)d_in[5];
    const float* bhh  = (const float*)d_in[6];
    const float* fcw  = (const float*)d_in[7];
    const float* fcb  = (const float*)d_in[8];
    float* out = (float*)d_out;

    cudaFuncSetAttribute(tc_persist, cudaFuncAttributeMaxDynamicSharedMemorySize, SMEM_P);
    cudaFuncSetAttribute(mma_gemm, cudaFuncAttributeMaxDynamicSharedMemorySize, GEMM_SMEM);

    lengths_kernel<<<B, T>>>(mask);
    embed_kernel<<<B * T, E / 4>>>(ids, emb);

    const size_t HS_OFF = (size_t)B * T * V;
    const size_t CS_OFF = HS_OFF + (size_t)L * B * H;

    for (int l = 0; l < L; l++) {
        const int W4 = G4 * E / 4;
        convert_w<<<(W4 + 255) / 256, 256>>>(Wih + (size_t)l * G4 * E, W4);

        mma_gemm<<<dim3(G4 / 128, (B * T) / 128), 256, GEMM_SMEM>>>(
            nullptr, bih + (size_t)l * G4, bhh + (size_t)l * G4, G4, G4, /*mode=*/0);

        reorder_whh<<<G4, 256>>>(Whh + (size_t)l * G4 * H);
        zero_hb<<<(B * H + 511) / 512, 512>>>();

        tc_persist<<<128, 256, SMEM_P>>>(
            out + HS_OFF + (size_t)l * B * H,
            out + CS_OFF + (size_t)l * B * H);
    }

    const int F4 = V * H / 4;
    convert_w<<<(F4 + 255) / 256, 256>>>(fcw, F4);

    mma_gemm<<<dim3((V + 127) / 128, (B * T) / 128), 256, GEMM_SMEM>>>(
        out, fcb, nullptr, V, V, /*mode=*/1);
}